// round 15
// baseline (speedup 1.0000x reference)
#include <cuda_runtime.h>
#include <cuda_bf16.h>
#include <math.h>

// Problem constants
constexpr int kT    = 1024;
constexpr int kDIM  = 2048;
constexpr int kH    = 16;
constexpr int kQLR  = 1024;
constexpr int kKVLR = 512;
constexpr int kNOPE = 128;
constexpr int kROPE = 64;
constexpr int kVD   = 128;
constexpr int kQKD  = 192;
constexpr int kIH   = 16;
constexpr int kID   = 128;
constexpr int kTOPK = 256;
constexpr int kCKEY = kKVLR + kROPE; // 576

// ---------------- scratch (static device globals; no allocation) -------------
__device__ float g_qr    [kT * kQLR];
__device__ float g_iqrn  [kT * kQLR];
__device__ float g_iq    [kT * kIH * kID];
__device__ float g_ik    [kT * kIH * kID];
__device__ float g_wgt   [kT * kIH];
__device__ float g_score [kT * kT];
__device__ int   g_topk  [kT * kTOPK];
__device__ float g_q     [kT * kH * kQKD];
__device__ float g_kva   [kT * kCKEY];
__device__ float g_kvkey [kT * kCKEY];
__device__ float g_qkey  [kT * kH * kCKEY];
__device__ float g_outv  [kT * kH * kVD];

// bf16 hi/lo pairs for the HMMA attention path
__device__ __nv_bfloat16 g_xh   [kT * kDIM],          g_xl   [kT * kDIM];
__device__ __nv_bfloat16 g_wqbh [kH * kQKD * kQLR],   g_wqbl [kH * kQKD * kQLR];
__device__ __nv_bfloat16 g_wkvah[kCKEY * kDIM],       g_wkval[kCKEY * kDIM];
__device__ __nv_bfloat16 g_wkvbh[kH * 256 * kKVLR],   g_wkvbl[kH * 256 * kKVLR];
__device__ __nv_bfloat16 g_woh  [kDIM * kDIM],        g_wol  [kDIM * kDIM];
__device__ __nv_bfloat16 g_qnh  [kT * kQLR],          g_qnl  [kT * kQLR];
__device__ __nv_bfloat16 g_qbth [kH * kT * kNOPE],    g_qbtl [kH * kT * kNOPE];
__device__ __nv_bfloat16 g_wkth [kH * kKVLR * kNOPE], g_wktl [kH * kKVLR * kNOPE];
__device__ __nv_bfloat16 g_olth [kH * kT * kKVLR],    g_oltl [kH * kT * kKVLR];
__device__ __nv_bfloat16 g_ovh  [kT * kDIM],          g_ovl  [kT * kDIM];

__device__ __forceinline__ float warp_sum(float v) {
#pragma unroll
    for (int o = 16; o; o >>= 1) v += __shfl_xor_sync(0xffffffffu, v, o);
    return v;
}

// =============================================================================
// gemm64 (score path): C[m,n] = sum_k A[m,k]*B[n,k]  (fp32, NT)
// Per-element FFMA chain (serial k order) identical to all passing rounds ->
// bit-stable top-k. K-chunk 16, double-buffered smem + register prefetch.
// =============================================================================
__global__ void __launch_bounds__(64) gemm64(
    const float* __restrict__ A, int lda,
    const float* __restrict__ B, int ldb,
    float* __restrict__ C, int ldc,
    int N, int K)
{
    __shared__ float As[2][16][64];
    __shared__ float Bs[2][16][64];
    int m0 = blockIdx.y * 64, n0 = blockIdx.x * 64;
    int tid = threadIdx.x;
    int tx = tid & 7, ty = tid >> 3;
    int lrow = tid >> 1;
    int lpc  = (tid & 1) * 4;

    float acc[8][8];
#pragma unroll
    for (int i = 0; i < 8; i++)
#pragma unroll
        for (int j = 0; j < 8; j++) acc[i][j] = 0.f;

    float4 va[2][2], vb[2][2];
    auto ldg = [&](int k0) {
#pragma unroll
        for (int i = 0; i < 2; i++) {
            int row = lrow + i * 32;
            bool bok = (n0 + row) < N;
#pragma unroll
            for (int p = 0; p < 2; p++) {
                int kp = lpc + p * 8;
                va[i][p] = *(const float4*)(A + (long long)(m0 + row) * lda + k0 + kp);
                vb[i][p] = make_float4(0.f, 0.f, 0.f, 0.f);
                if (bok)
                    vb[i][p] = *(const float4*)(B + (long long)(n0 + row) * ldb + k0 + kp);
            }
        }
    };

    const int nch = K >> 4;
    ldg(0);
    for (int c = 0; c < nch; c++) {
        int buf = c & 1;
#pragma unroll
        for (int i = 0; i < 2; i++) {
            int row = lrow + i * 32;
#pragma unroll
            for (int p = 0; p < 2; p++) {
                int kp = lpc + p * 8;
                As[buf][kp + 0][row] = va[i][p].x; As[buf][kp + 1][row] = va[i][p].y;
                As[buf][kp + 2][row] = va[i][p].z; As[buf][kp + 3][row] = va[i][p].w;
                Bs[buf][kp + 0][row] = vb[i][p].x; Bs[buf][kp + 1][row] = vb[i][p].y;
                Bs[buf][kp + 2][row] = vb[i][p].z; Bs[buf][kp + 3][row] = vb[i][p].w;
            }
        }
        __syncthreads();
        if (c + 1 < nch) ldg((c + 1) << 4);
#pragma unroll
        for (int k = 0; k < 16; k++) {
            float a[8], b[8];
            *(float4*)&a[0] = *(const float4*)&As[buf][k][ty * 8];
            *(float4*)&a[4] = *(const float4*)&As[buf][k][ty * 8 + 4];
            *(float4*)&b[0] = *(const float4*)&Bs[buf][k][tx * 8];
            *(float4*)&b[4] = *(const float4*)&Bs[buf][k][tx * 8 + 4];
#pragma unroll
            for (int i = 0; i < 8; i++)
#pragma unroll
                for (int j = 0; j < 8; j++) acc[i][j] += a[i] * b[j];
        }
    }
#pragma unroll
    for (int i = 0; i < 8; i++) {
        int m = m0 + ty * 8 + i;
#pragma unroll
        for (int j = 0; j < 8; j++) {
            int n = n0 + tx * 8 + j;
            if (n < N) C[(long long)m * ldc + n] = acc[i][j];
        }
    }
}

// =============================================================================
// bf16x3 HMMA NT GEMM (attention path, smooth): AhBh + AhBl + AlBh.
// =============================================================================
__device__ __forceinline__ unsigned cvta_shared_u32(const void* p) {
    unsigned a;
    asm("{ .reg .u64 t; cvta.to.shared.u64 t, %1; cvt.u32.u64 %0, t; }"
        : "=r"(a) : "l"(p));
    return a;
}
__device__ __forceinline__ void cp16(unsigned dst, const void* src, unsigned sz) {
    asm volatile("cp.async.cg.shared.global [%0], [%1], 16, %2;"
                 :: "r"(dst), "l"(src), "r"(sz));
}
__device__ __forceinline__ void cp16ca(unsigned dst, const void* src) {
    asm volatile("cp.async.ca.shared.global [%0], [%1], 16;"
                 :: "r"(dst), "l"(src));
}
__device__ __forceinline__ void cp_commit() { asm volatile("cp.async.commit_group;"); }
__device__ __forceinline__ void cp_wait1()  { asm volatile("cp.async.wait_group 1;"); }
__device__ __forceinline__ void cp_wait0()  { asm volatile("cp.async.wait_group 0;"); }
__device__ __forceinline__ void ldsm4(unsigned& r0, unsigned& r1, unsigned& r2,
                                      unsigned& r3, unsigned addr) {
    asm volatile("ldmatrix.sync.aligned.m8n8.x4.shared.b16 {%0,%1,%2,%3}, [%4];"
                 : "=r"(r0), "=r"(r1), "=r"(r2), "=r"(r3) : "r"(addr));
}
__device__ __forceinline__ void mma_bf16(float& c0, float& c1, float& c2, float& c3,
                                         unsigned a0, unsigned a1, unsigned a2,
                                         unsigned a3, unsigned b0, unsigned b1) {
    asm volatile(
        "mma.sync.aligned.m16n8k16.row.col.f32.bf16.bf16.f32 "
        "{%0,%1,%2,%3}, {%4,%5,%6,%7}, {%8,%9}, {%0,%1,%2,%3};"
        : "+f"(c0), "+f"(c1), "+f"(c2), "+f"(c3)
        : "r"(a0), "r"(a1), "r"(a2), "r"(a3), "r"(b0), "r"(b1));
}

constexpr int kPitch  = 80;
constexpr int kMatB   = 128 * kPitch;
constexpr int kStageB = 4 * kMatB;

__global__ void __launch_bounds__(256) gemm_nt_mma(
    const __nv_bfloat16* __restrict__ Ah, const __nv_bfloat16* __restrict__ Al,
    int lda, long long sA,
    const __nv_bfloat16* __restrict__ Bh, const __nv_bfloat16* __restrict__ Bl,
    int ldb, long long sB,
    float* __restrict__ C, int ldc, long long sC,
    int N, int K)
{
    extern __shared__ char smem[];
    const unsigned sbase = cvta_shared_u32(smem);
    const int z = blockIdx.z;
    Ah += z * sA; Al += z * sA; Bh += z * sB; Bl += z * sB; C += z * sC;
    const int tid = threadIdx.x;
    const int wid = tid >> 5, lane = tid & 31;
    const int m0 = blockIdx.y * 128, n0 = blockIdx.x * 128;
    const int wm0 = (wid & 1) * 64;
    const int wn0 = (wid >> 1) * 32;

    float acc[4][4][4];
#pragma unroll
    for (int i = 0; i < 4; i++)
#pragma unroll
        for (int j = 0; j < 4; j++)
#pragma unroll
            for (int e = 0; e < 4; e++) acc[i][j][e] = 0.f;

    const int nch = K >> 5;

    auto issue_stage = [&](int c, int buf) {
        const int k0 = c << 5;
        const unsigned stage = sbase + buf * kStageB;
#pragma unroll
        for (int i = 0; i < 8; i++) {
            int idx = tid + (i << 8);
            int mat = idx >> 9, row = (idx >> 2) & 127, piece = idx & 3;
            unsigned dst = stage + mat * kMatB + row * kPitch + piece * 16;
            const __nv_bfloat16* srcp;
            unsigned sz = 16;
            if (mat == 0)      srcp = Ah + (size_t)(m0 + row) * lda + k0 + piece * 8;
            else if (mat == 1) srcp = Al + (size_t)(m0 + row) * lda + k0 + piece * 8;
            else {
                int r = n0 + row;
                int rr = (r < N) ? r : 0;
                sz = (r < N) ? 16u : 0u;
                srcp = ((mat == 2) ? Bh : Bl) + (size_t)rr * ldb + k0 + piece * 8;
            }
            cp16(dst, srcp, sz);
        }
    };

    issue_stage(0, 0); cp_commit();
    if (nch > 1) issue_stage(1, 1);
    cp_commit();

    const int rowA = wm0 + (lane & 15);
    const int kA   = (lane >> 4) << 3;
    const int rowB = wn0 + (lane & 15);
    const int kB   = (lane >> 4) << 3;

    for (int c = 0; c < nch; c++) {
        cp_wait1();
        __syncthreads();
        const unsigned stage = sbase + (c & 1) * kStageB;
        const unsigned aHb = stage;
        const unsigned aLb = stage + kMatB;
        const unsigned bHb = stage + 2 * kMatB;
        const unsigned bLb = stage + 3 * kMatB;

#pragma unroll
        for (int ks = 0; ks < 2; ks++) {
            const int kb = ks << 4;
            unsigned ah[4][4], al[4][4], bh[4][2], bl[4][2];
#pragma unroll
            for (int i = 0; i < 4; i++) {
                unsigned off = (unsigned)((rowA + 16 * i) * kPitch + (kb + kA) * 2);
                ldsm4(ah[i][0], ah[i][1], ah[i][2], ah[i][3], aHb + off);
                ldsm4(al[i][0], al[i][1], al[i][2], al[i][3], aLb + off);
            }
#pragma unroll
            for (int p = 0; p < 2; p++) {
                unsigned off = (unsigned)((rowB + 16 * p) * kPitch + (kb + kB) * 2);
                unsigned r0, r1, r2, r3;
                ldsm4(r0, r1, r2, r3, bHb + off);
                bh[2 * p][0] = r0; bh[2 * p][1] = r2;
                bh[2 * p + 1][0] = r1; bh[2 * p + 1][1] = r3;
                ldsm4(r0, r1, r2, r3, bLb + off);
                bl[2 * p][0] = r0; bl[2 * p][1] = r2;
                bl[2 * p + 1][0] = r1; bl[2 * p + 1][1] = r3;
            }
#pragma unroll
            for (int i = 0; i < 4; i++)
#pragma unroll
                for (int j = 0; j < 4; j++) {
                    mma_bf16(acc[i][j][0], acc[i][j][1], acc[i][j][2], acc[i][j][3],
                             ah[i][0], ah[i][1], ah[i][2], ah[i][3],
                             bh[j][0], bh[j][1]);
                    mma_bf16(acc[i][j][0], acc[i][j][1], acc[i][j][2], acc[i][j][3],
                             ah[i][0], ah[i][1], ah[i][2], ah[i][3],
                             bl[j][0], bl[j][1]);
                    mma_bf16(acc[i][j][0], acc[i][j][1], acc[i][j][2], acc[i][j][3],
                             al[i][0], al[i][1], al[i][2], al[i][3],
                             bh[j][0], bh[j][1]);
                }
        }
        __syncthreads();
        if (c + 2 < nch) issue_stage(c + 2, c & 1);
        cp_commit();
    }
    cp_wait0();

    const int erow = lane >> 2;
    const int ecol = (lane & 3) * 2;
#pragma unroll
    for (int i = 0; i < 4; i++)
#pragma unroll
        for (int j = 0; j < 4; j++) {
            int n = n0 + wn0 + 8 * j + ecol;
            if (n < N) {
                int m = m0 + wm0 + 16 * i + erow;
                *(float2*)(C + (size_t)m * ldc + n) =
                    make_float2(acc[i][j][0], acc[i][j][1]);
                *(float2*)(C + (size_t)(m + 8) * ldc + n) =
                    make_float2(acc[i][j][2], acc[i][j][3]);
            }
        }
}

// ---------------- fp32 -> bf16 hi/lo split ------------------------------------
__device__ __forceinline__ unsigned short bfu(__nv_bfloat16 b) {
    return *reinterpret_cast<unsigned short*>(&b);
}
__global__ void split_kernel(const float4* __restrict__ in,
                             uint2* __restrict__ hi, uint2* __restrict__ lo, int n4)
{
    int i = blockIdx.x * 256 + threadIdx.x;
    if (i >= n4) return;
    float4 v = in[i];
    __nv_bfloat16 hx = __float2bfloat16(v.x), hy = __float2bfloat16(v.y);
    __nv_bfloat16 hz = __float2bfloat16(v.z), hw = __float2bfloat16(v.w);
    __nv_bfloat16 lx = __float2bfloat16(v.x - __bfloat162float(hx));
    __nv_bfloat16 ly = __float2bfloat16(v.y - __bfloat162float(hy));
    __nv_bfloat16 lz = __float2bfloat16(v.z - __bfloat162float(hz));
    __nv_bfloat16 lw = __float2bfloat16(v.w - __bfloat162float(hw));
    uint2 ho, loo;
    ho.x  = (unsigned)bfu(hx) | ((unsigned)bfu(hy) << 16);
    ho.y  = (unsigned)bfu(hz) | ((unsigned)bfu(hw) << 16);
    loo.x = (unsigned)bfu(lx) | ((unsigned)bfu(ly) << 16);
    loo.y = (unsigned)bfu(lz) | ((unsigned)bfu(lw) << 16);
    hi[i] = ho; lo[i] = loo;
}

// =============================================================================
// SCORE-PATH ELEMENTWISE KERNELS — numerics unchanged from passing rounds.
// =============================================================================

__global__ void qrnorm_kernel(const float* __restrict__ qr,
                              const float* __restrict__ qnw,
                              const float* __restrict__ iqnw,
                              __nv_bfloat16* __restrict__ qh,
                              __nv_bfloat16* __restrict__ ql,
                              float* __restrict__ iqn)
{
    int t = blockIdx.x;
    __shared__ float sred[16];
    float s = 0.f;
    for (int i = threadIdx.x; i < kQLR; i += 512) {
        float v = qr[t * kQLR + i]; s += v * v;
    }
    s = warp_sum(s);
    if ((threadIdx.x & 31) == 0) sred[threadIdx.x >> 5] = s;
    __syncthreads();
    float tot = 0.f;
#pragma unroll
    for (int i = 0; i < 16; i++) tot += sred[i];
    float rstd = rsqrtf(tot * (1.f / kQLR) + 1e-6f);
    for (int i = threadIdx.x; i < kQLR; i += 512) {
        float v = qr[t * kQLR + i] * rstd;
        float a = v * qnw[i];
        __nv_bfloat16 h = __float2bfloat16(a);
        qh[t * kQLR + i] = h;
        ql[t * kQLR + i] = __float2bfloat16(a - __bfloat162float(h));
        iqn[t * kQLR + i] = v * iqnw[i];
    }
}

__global__ void idx_prep_kernel(float* __restrict__ data,
                                const float* __restrict__ rc,
                                const float* __restrict__ rs,
                                const float* __restrict__ lnw,
                                const float* __restrict__ lnb,
                                int do_ln)
{
    int t = blockIdx.x >> 4;
    int h = blockIdx.x & 15;
    float* v = data + (size_t)t * (kIH * kID) + h * kID;
    int d = threadIdx.x;
    __shared__ float sv[128];
    __shared__ float sred[4];
    float x = v[d];
    if (do_ln) {
        float s = warp_sum(x);
        if ((d & 31) == 0) sred[d >> 5] = s;
        __syncthreads();
        float mean = (sred[0] + sred[1] + sred[2] + sred[3]) * (1.f / 128.f);
        float c = x - mean;
        __syncthreads();
        float s2 = warp_sum(c * c);
        if ((d & 31) == 0) sred[d >> 5] = s2;
        __syncthreads();
        float var = (sred[0] + sred[1] + sred[2] + sred[3]) * (1.f / 128.f);
        x = c * rsqrtf(var + 1e-5f) * lnw[d] + lnb[d];
    }
    sv[d] = x;
    __syncthreads();
    float out;
    if (d < 32) {
        out = sv[d] * rc[t * 32 + d] - sv[d + 32] * rs[t * 32 + d];
    } else if (d < 64) {
        int j = d - 32;
        out = sv[j] * rs[t * 32 + j] + sv[j + 32] * rc[t * 32 + j];
    } else {
        out = x;
    }
    v[d] = out;
}

__global__ void wgt_kernel(const float* __restrict__ x,
                           const float* __restrict__ wproj,
                           float* __restrict__ wgt)
{
    int t = blockIdx.x;
    __shared__ float sx[kDIM];
    for (int i = threadIdx.x; i < kDIM; i += 512) sx[i] = x[(size_t)t * kDIM + i];
    __syncthreads();
    int w = threadIdx.x >> 5, lane = threadIdx.x & 31;
    float acc = 0.f;
    for (int i = lane; i < kDIM; i += 32) acc += sx[i] * wproj[w * kDIM + i];
    acc = warp_sum(acc);
    if (lane == 0) wgt[t * kIH + w] = acc * 0.022097086912079613f;
}

__global__ void __launch_bounds__(256) score_kernel(
    const float* __restrict__ iq, const float* __restrict__ ik,
    const float* __restrict__ wgt, float* __restrict__ score)
{
    int s0 = blockIdx.x * 64, t0 = blockIdx.y * 64;
    if (s0 > t0 + 63) return;
    __shared__ float As[16][64], Bs[16][64];
    int tid = threadIdx.x;
    int tx = tid & 15, ty = tid >> 4;
    int r = tid >> 2, kq = (tid & 3) * 4;
    float acc[4][4];
#pragma unroll
    for (int i = 0; i < 4; i++)
#pragma unroll
        for (int j = 0; j < 4; j++) acc[i][j] = 0.f;

    for (int h = 0; h < 16; h++) {
        float hacc[4][4];
#pragma unroll
        for (int i = 0; i < 4; i++)
#pragma unroll
            for (int j = 0; j < 4; j++) hacc[i][j] = 0.f;
        for (int k0 = 0; k0 < 128; k0 += 16) {
            float4 av = *(const float4*)&iq[(size_t)(t0 + r) * 2048 + h * 128 + k0 + kq];
            float4 bv = *(const float4*)&ik[(size_t)(s0 + r) * 2048 + h * 128 + k0 + kq];
            As[kq][r] = av.x; As[kq + 1][r] = av.y;
            As[kq + 2][r] = av.z; As[kq + 3][r] = av.w;
            Bs[kq][r] = bv.x; Bs[kq + 1][r] = bv.y;
            Bs[kq + 2][r] = bv.z; Bs[kq + 3][r] = bv.w;
            __syncthreads();
#pragma unroll
            for (int k = 0; k < 16; k++) {
                float a[4], b[4];
#pragma unroll
                for (int i = 0; i < 4; i++) a[i] = As[k][ty * 4 + i];
#pragma unroll
                for (int j = 0; j < 4; j++) b[j] = Bs[k][tx * 4 + j];
#pragma unroll
                for (int i = 0; i < 4; i++)
#pragma unroll
                    for (int j = 0; j < 4; j++) hacc[i][j] += a[i] * b[j];
            }
            __syncthreads();
        }
#pragma unroll
        for (int i = 0; i < 4; i++) {
            float wv = wgt[(t0 + ty * 4 + i) * kIH + h];
#pragma unroll
            for (int j = 0; j < 4; j++)
                acc[i][j] += fmaxf(hacc[i][j], 0.f) * wv;
        }
    }
#pragma unroll
    for (int i = 0; i < 4; i++)
#pragma unroll
        for (int j = 0; j < 4; j++)
            score[(size_t)(t0 + ty * 4 + i) * kT + s0 + tx * 4 + j] = acc[i][j];
}

// top-256 per row; t = blockIdx.x + t0 so it can run in token-halves.
__global__ void __launch_bounds__(512) topk_kernel(const float* __restrict__ score,
                                                   int* __restrict__ topk, int t0)
{
    int t = blockIdx.x + t0;
    __shared__ unsigned long long keys[1024];
    for (int i = threadIdx.x; i < 1024; i += 512) {
        float v = (i <= t) ? score[(size_t)t * kT + i] : __int_as_float(0xff800000);
        unsigned int fb = __float_as_uint(v);
        fb = (fb & 0x80000000u) ? ~fb : (fb | 0x80000000u);
        keys[i] = ((unsigned long long)fb << 32) | (unsigned int)(1023 - i);
    }
    __syncthreads();
    for (int k = 2; k <= 1024; k <<= 1) {
        for (int j = k >> 1; j > 0; j >>= 1) {
            for (int i = threadIdx.x; i < 1024; i += 512) {
                int ixj = i ^ j;
                if (ixj > i) {
                    unsigned long long a = keys[i], b = keys[ixj];
                    bool seg = ((i & k) == 0);
                    bool sw = seg ? (a < b) : (a > b);
                    if (sw) { keys[i] = b; keys[ixj] = a; }
                }
            }
            __syncthreads();
        }
    }
    if (threadIdx.x < 256)
        topk[t * kTOPK + threadIdx.x] =
            1023 - (int)(keys[threadIdx.x] & 0xFFFFFFFFu);
}

// =============================================================================
// ATTENTION PATH helpers
// =============================================================================

__global__ void wk_transpose(const float* __restrict__ wkv_b,
                             __nv_bfloat16* __restrict__ wkTh,
                             __nv_bfloat16* __restrict__ wkTl)
{
    __shared__ float tile[32][33];
    int h = blockIdx.z;
    int c0 = blockIdx.x * 32, d0 = blockIdx.y * 32;
    int tx = threadIdx.x, ty = threadIdx.y;
#pragma unroll
    for (int k = 0; k < 4; k++)
        tile[ty + 8 * k][tx] = wkv_b[(size_t)(h * 256 + d0 + ty + 8 * k) * 512 + c0 + tx];
    __syncthreads();
#pragma unroll
    for (int k = 0; k < 4; k++) {
        float v = tile[tx][ty + 8 * k];
        size_t o = (size_t)h * 65536 + (size_t)(c0 + ty + 8 * k) * 128 + d0 + tx;
        __nv_bfloat16 hh = __float2bfloat16(v);
        wkTh[o] = hh;
        wkTl[o] = __float2bfloat16(v - __bfloat162float(hh));
    }
}

__global__ void qb_repack(const float* __restrict__ qb,
                          __nv_bfloat16* __restrict__ qbth,
                          __nv_bfloat16* __restrict__ qbtl)
{
    int t = blockIdx.x;
    for (int i = threadIdx.x; i < 2048; i += 512) {
        int h = i >> 7, d = i & 127;
        float v = qb[(size_t)t * 3072 + h * 192 + d];
        size_t o = (size_t)(h * 1024 + t) * 128 + d;
        __nv_bfloat16 hh = __float2bfloat16(v);
        qbth[o] = hh;
        qbtl[o] = __float2bfloat16(v - __bfloat162float(hh));
    }
}

__global__ void kvprep_kernel(const float* __restrict__ kva,
                              const float* __restrict__ kvnw,
                              const float* __restrict__ rc,
                              const float* __restrict__ rs,
                              float* __restrict__ kvkey)
{
    int t = blockIdx.x, tid = threadIdx.x;
    __shared__ float sred[16];
    float x = kva[(size_t)t * kCKEY + tid];
    float s = warp_sum(x * x);
    if ((tid & 31) == 0) sred[tid >> 5] = s;
    __syncthreads();
    float tot = 0.f;
#pragma unroll
    for (int i = 0; i < 16; i++) tot += sred[i];
    float rstd = rsqrtf(tot * (1.f / kKVLR) + 1e-6f);
    kvkey[(size_t)t * kCKEY + tid] = x * rstd * kvnw[tid];
    if (tid < 32) {
        float x1 = kva[(size_t)t * kCKEY + 512 + tid];
        float x2 = kva[(size_t)t * kCKEY + 544 + tid];
        float c = rc[t * 32 + tid], sn = rs[t * 32 + tid];
        kvkey[(size_t)t * kCKEY + 512 + tid] = x1 * c - x2 * sn;
        kvkey[(size_t)t * kCKEY + 544 + tid] = x1 * sn + x2 * c;
    }
}

__global__ void qprep_kernel(const float* __restrict__ q,
                             const float* __restrict__ rc,
                             const float* __restrict__ rs,
                             float* __restrict__ qkey)
{
    int t = blockIdx.x;
    int h = threadIdx.x >> 5, j = threadIdx.x & 31;
    const float* b = q + (size_t)t * (kH * kQKD) + h * kQKD;
    float x1 = b[128 + j], x2 = b[160 + j];
    float c = rc[t * 32 + j], sn = rs[t * 32 + j];
    float* o = qkey + (size_t)t * (kH * kCKEY) + h * kCKEY;
    o[512 + j] = x1 * c - x2 * sn;
    o[544 + j] = x1 * sn + x2 * c;
}

// fused sparse attention; t = blockIdx.x + t0 (token-half launches)
__global__ void __launch_bounds__(512) attn_kernel(
    const float* __restrict__ qkey, const float* __restrict__ kvkey,
    const int* __restrict__ topk,
    __nv_bfloat16* __restrict__ olth, __nv_bfloat16* __restrict__ oltl, int t0in)
{
    extern __shared__ float sm[];
    float* sq    = sm;                  // 9216
    float* stile = sm + 9216;           // 2 x 9216 (double buffered, pitch 36)
    float* slog2 = sm + 9216;           // reuse of stileA (256 x pitch 20)
    float* slog  = sm + 27648;          // 4096 ([h][k])
    int*   sidx  = (int*)(sm + 31744);  // 256
    const unsigned stile_u32 = cvta_shared_u32(stile);
    int t = blockIdx.x + t0in, tid = threadIdx.x;
    for (int i = tid; i < 9216; i += 512) sq[i] = qkey[(size_t)t * 9216 + i];
    if (tid < 256) sidx[tid] = topk[t * kTOPK + tid];
    __syncthreads();

    const float scale = 0.07216878364870323f; // 192^-0.5

    // phase 1: logits = sel(256x576) @ q^T(576x16), cp.async double-buffered
    {
        int rg = tid >> 3;
        int hg = tid & 7;
        float pacc[4][2];
#pragma unroll
        for (int i = 0; i < 4; i++) { pacc[i][0] = 0.f; pacc[i][1] = 0.f; }

        auto issue = [&](int cc, int buf) {
            int c0 = cc * 32;
#pragma unroll
            for (int i = 0; i < 4; i++) {
                int idx = tid + 512 * i;
                int r = idx >> 3;
                int p = (idx & 7) * 4;
                cp16ca(stile_u32 + (unsigned)(buf * 9216 + r * 36 + p) * 4u,
                       &kvkey[(size_t)sidx[r] * kCKEY + c0 + p]);
            }
        };

        issue(0, 0); cp_commit();
        for (int cc = 0; cc < 18; cc++) {
            int buf = cc & 1;
            cp_wait0();
            __syncthreads();
            if (cc + 1 < 18) { issue(cc + 1, 1 - buf); cp_commit(); }
            const float* st = stile + buf * 9216;
#pragma unroll
            for (int c4 = 0; c4 < 8; c4++) {
                int c0 = cc * 32;
                float4 q0 = *(const float4*)&sq[(hg * 2 + 0) * kCKEY + c0 + c4 * 4];
                float4 q1 = *(const float4*)&sq[(hg * 2 + 1) * kCKEY + c0 + c4 * 4];
#pragma unroll
                for (int i = 0; i < 4; i++) {
                    float4 s = *(const float4*)&st[(rg * 4 + i) * 36 + c4 * 4];
                    pacc[i][0] += s.x * q0.x + s.y * q0.y + s.z * q0.z + s.w * q0.w;
                    pacc[i][1] += s.x * q1.x + s.y * q1.y + s.z * q1.z + s.w * q1.w;
                }
            }
        }
        __syncthreads();
#pragma unroll
        for (int i = 0; i < 4; i++) {
            int k = rg * 4 + i;
            int idx = sidx[k];
            float ninf = __int_as_float(0xff800000);
#pragma unroll
            for (int hh = 0; hh < 2; hh++) {
                int h = hg * 2 + hh;
                slog[h * 256 + k] = (idx <= t) ? pacc[i][hh] * scale : ninf;
            }
        }
    }
    __syncthreads();

    // softmax per head -> slog2 in [k][pitch 20]
    {
        int hh = tid >> 5, lane = tid & 31;
        float vals[8];
        float m = __int_as_float(0xff800000);
#pragma unroll
        for (int i = 0; i < 8; i++) {
            vals[i] = slog[hh * 256 + lane + 32 * i];
            m = fmaxf(m, vals[i]);
        }
#pragma unroll
        for (int o = 16; o; o >>= 1) m = fmaxf(m, __shfl_xor_sync(0xffffffffu, m, o));
        float s = 0.f;
#pragma unroll
        for (int i = 0; i < 8; i++) {
            float e = (vals[i] > -1e30f) ? __expf(vals[i] - m) : 0.f;
            vals[i] = e; s += e;
        }
        s = warp_sum(s);
        float inv = 1.f / s;
        __syncthreads();
#pragma unroll
        for (int i = 0; i < 8; i++)
            slog2[(lane + 32 * i) * 20 + hh] = vals[i] * inv;
    }
    __syncthreads();

    // phase 2
    {
        int c = tid;
        float acc[16];
#pragma unroll
        for (int i = 0; i < 16; i++) acc[i] = 0.f;
        for (int k = 0; k < 256; k++) {
            float v = kvkey[(size_t)sidx[k] * kCKEY + c];
            float4 w0 = *(const float4*)&slog2[k * 20 + 0];
            float4 w1 = *(const float4*)&slog2[k * 20 + 4];
            float4 w2 = *(const float4*)&slog2[k * 20 + 8];
            float4 w3 = *(const float4*)&slog2[k * 20 + 12];
            acc[0]  += w0.x * v; acc[1]  += w0.y * v; acc[2]  += w0.z * v; acc[3]  += w0.w * v;
            acc[4]  += w1.x * v; acc[5]  += w1.y * v; acc[6]  += w1.z * v; acc[7]  += w1.w * v;
            acc[8]  += w2.x * v; acc[9]  += w2.y * v; acc[10] += w2.z * v; acc[11] += w2.w * v;
            acc[12] += w3.x * v; acc[13] += w3.y * v; acc[14] += w3.z * v; acc[15] += w3.w * v;
        }
#pragma unroll
        for (int hh = 0; hh < 16; hh++) {
            float v = acc[hh];
            size_t o = (size_t)(hh * kT + t) * kKVLR + c;
            __nv_bfloat16 h = __float2bfloat16(v);
            olth[o] = h;
            oltl[o] = __float2bfloat16(v - __bfloat162float(h));
        }
    }
}

// ---------------- host launch -------------------------------------------------
static inline void splitOn(cudaStream_t s, const float* src,
                           __nv_bfloat16* h, __nv_bfloat16* l, int n) {
    int n4 = n / 4;
    split_kernel<<<(n4 + 255) / 256, 256, 0, s>>>((const float4*)src,
                                                  (uint2*)h, (uint2*)l, n4);
}

extern "C" void kernel_launch(void* const* d_in, const int* in_sizes, int n_in,
                              void* d_out, int out_size)
{
    const float* x        = (const float*)d_in[0];
    const float* rc       = (const float*)d_in[1];
    const float* rs       = (const float*)d_in[2];
    const float* wq_a     = (const float*)d_in[3];
    const float* q_norm_w = (const float*)d_in[4];
    const float* wq_b     = (const float*)d_in[5];
    const float* wkv_a    = (const float*)d_in[6];
    const float* kv_norm_w= (const float*)d_in[7];
    const float* wkv_b    = (const float*)d_in[8];
    const float* wo       = (const float*)d_in[9];
    const float* iq_norm_w= (const float*)d_in[10];
    const float* iwq_b    = (const float*)d_in[11];
    const float* iwk      = (const float*)d_in[12];
    const float* k_norm_w = (const float*)d_in[13];
    const float* k_norm_b = (const float*)d_in[14];
    const float* wproj    = (const float*)d_in[15];
    float* out = (float*)d_out;

    float *qr, *iqrn, *iqb, *ikb, *wgt, *score, *qb, *kva, *kvkey, *qkey, *outv;
    int* topk;
    __nv_bfloat16 *xh, *xl, *wqbh, *wqbl, *wkvah, *wkval, *wkvbh, *wkvbl, *woh, *wol;
    __nv_bfloat16 *qnh, *qnl, *qbth, *qbtl, *wkth, *wktl, *olth, *oltl, *ovh, *ovl;

    cudaGetSymbolAddress((void**)&qr,    g_qr);
    cudaGetSymbolAddress((void**)&iqrn,  g_iqrn);
    cudaGetSymbolAddress((void**)&iqb,   g_iq);
    cudaGetSymbolAddress((void**)&ikb,   g_ik);
    cudaGetSymbolAddress((void**)&wgt,   g_wgt);
    cudaGetSymbolAddress((void**)&score, g_score);
    cudaGetSymbolAddress((void**)&topk,  g_topk);
    cudaGetSymbolAddress((void**)&qb,    g_q);
    cudaGetSymbolAddress((void**)&kva,   g_kva);
    cudaGetSymbolAddress((void**)&kvkey, g_kvkey);
    cudaGetSymbolAddress((void**)&qkey,  g_qkey);
    cudaGetSymbolAddress((void**)&outv,  g_outv);
    cudaGetSymbolAddress((void**)&xh,    g_xh);    cudaGetSymbolAddress((void**)&xl,    g_xl);
    cudaGetSymbolAddress((void**)&wqbh,  g_wqbh);  cudaGetSymbolAddress((void**)&wqbl,  g_wqbl);
    cudaGetSymbolAddress((void**)&wkvah, g_wkvah); cudaGetSymbolAddress((void**)&wkval, g_wkval);
    cudaGetSymbolAddress((void**)&wkvbh, g_wkvbh); cudaGetSymbolAddress((void**)&wkvbl, g_wkvbl);
    cudaGetSymbolAddress((void**)&woh,   g_woh);   cudaGetSymbolAddress((void**)&wol,   g_wol);
    cudaGetSymbolAddress((void**)&qnh,   g_qnh);   cudaGetSymbolAddress((void**)&qnl,   g_qnl);
    cudaGetSymbolAddress((void**)&qbth,  g_qbth);  cudaGetSymbolAddress((void**)&qbtl,  g_qbtl);
    cudaGetSymbolAddress((void**)&wkth,  g_wkth);  cudaGetSymbolAddress((void**)&wktl,  g_wktl);
    cudaGetSymbolAddress((void**)&olth,  g_olth);  cudaGetSymbolAddress((void**)&oltl,  g_oltl);
    cudaGetSymbolAddress((void**)&ovh,   g_ovh);   cudaGetSymbolAddress((void**)&ovl,   g_ovl);

    const int ATTN_SMEM = (31744 + 256) * 4; // 128000 B
    cudaFuncSetAttribute(attn_kernel, cudaFuncAttributeMaxDynamicSharedMemorySize, ATTN_SMEM);
    cudaFuncSetAttribute(gemm_nt_mma, cudaFuncAttributeMaxDynamicSharedMemorySize, 2 * kStageB);
    const int MMASM = 2 * kStageB;
    const int HT = kT / 2;

    static cudaStream_t s1 = nullptr;
    static cudaEvent_t evFork = nullptr, evQN = nullptr, evPrep = nullptr;
    static cudaEvent_t evTopk1 = nullptr, evTopk2 = nullptr, evW = nullptr;
    if (!s1) {
        cudaStreamCreateWithFlags(&s1, cudaStreamNonBlocking);
        cudaEventCreateWithFlags(&evFork,  cudaEventDisableTiming);
        cudaEventCreateWithFlags(&evQN,    cudaEventDisableTiming);
        cudaEventCreateWithFlags(&evPrep,  cudaEventDisableTiming);
        cudaEventCreateWithFlags(&evTopk1, cudaEventDisableTiming);
        cudaEventCreateWithFlags(&evTopk2, cudaEventDisableTiming);
        cudaEventCreateWithFlags(&evW,     cudaEventDisableTiming);
    }
    cudaStream_t M = 0;

    // ---- fork ----
    cudaEventRecord(evFork, M);
    cudaStreamWaitEvent(s1, evFork, 0);

    // S1: wk_transpose (input-only), then score branch (x-only part)
    wk_transpose<<<dim3(16, 4, 16), dim3(32, 8), 0, s1>>>(wkv_b, wkth, wktl);
    cudaEventRecord(evPrep, s1);
    gemm64<<<dim3(32, 16), 64, 0, s1>>>(x, kDIM, iwk, kDIM, ikb, 2048, 2048, kDIM);
    idx_prep_kernel<<<kT * kIH, 128, 0, s1>>>(ikb, rc, rs, k_norm_w, k_norm_b, 1);
    wgt_kernel<<<kT, 512, 0, s1>>>(x, wproj, wgt);

    // M: qr + qrnorm first (feeds score branch)
    gemm64<<<dim3(16, 16), 64, 0, M>>>(x, kDIM, wq_a, kDIM, qr, kQLR, kQLR, kDIM);
    qrnorm_kernel<<<kT, 512, 0, M>>>(qr, q_norm_w, iq_norm_w, qnh, qnl, iqrn);
    cudaEventRecord(evQN, M);

    // S1: rest of score path; topk in two token-halves
    cudaStreamWaitEvent(s1, evQN, 0);
    gemm64<<<dim3(32, 16), 64, 0, s1>>>(iqrn, kQLR, iwq_b, kQLR, iqb, 2048, 2048, kQLR);
    idx_prep_kernel<<<kT * kIH, 128, 0, s1>>>(iqb, rc, rs, nullptr, nullptr, 0);
    score_kernel<<<dim3(16, 16), 256, 0, s1>>>(iqb, ikb, wgt, score);
    topk_kernel<<<HT, 512, 0, s1>>>(score, topk, 0);
    cudaEventRecord(evTopk1, s1);
    topk_kernel<<<HT, 512, 0, s1>>>(score, topk, HT);
    cudaEventRecord(evTopk2, s1);
    // S1 post-topk: weight splits consumed only after the join
    splitOn(s1, wkv_b, wkvbh, wkvbl, kH * 256 * kKVLR);
    splitOn(s1, wo,    woh,   wol,   kDIM * kDIM);
    cudaEventRecord(evW, s1);

    // M: attention path up to qkey
    splitOn(M, wq_b, wqbh, wqbl, kH * kQKD * kQLR);
    gemm_nt_mma<<<dim3(24, 8, 1), 256, MMASM, M>>>(
        qnh, qnl, kQLR, 0, wqbh, wqbl, kQLR, 0,
        qb, kH * kQKD, 0, kH * kQKD, kQLR);
    splitOn(M, x,     xh,    xl,    kT * kDIM);
    splitOn(M, wkv_a, wkvah, wkval, kCKEY * kDIM);
    gemm_nt_mma<<<dim3(5, 8, 1), 256, MMASM, M>>>(
        xh, xl, kDIM, 0, wkvah, wkval, kDIM, 0,
        kva, kCKEY, 0, kCKEY, kDIM);
    kvprep_kernel<<<kT, 512, 0, M>>>(kva, kv_norm_w, rc, rs, kvkey);
    qb_repack<<<kT, 512, 0, M>>>(qb, qbth, qbtl);
    qprep_kernel<<<kT, 512, 0, M>>>(qb, rc, rs, qkey);
    cudaStreamWaitEvent(M, evPrep, 0);
    gemm_nt_mma<<<dim3(4, 8, 16), 256, MMASM, M>>>(
        qbth, qbtl, kNOPE, (long long)kT * kNOPE,
        wkth, wktl, kNOPE, (long long)kKVLR * kNOPE,
        qkey, kH * kCKEY, kCKEY, kKVLR, kNOPE);

    // ---- join: attn in token-halves (h1 overlaps topk h2); full-width tail ----
    cudaStreamWaitEvent(M, evTopk1, 0);
    attn_kernel<<<HT, 512, ATTN_SMEM, M>>>(qkey, kvkey, topk, olth, oltl, 0);
    cudaStreamWaitEvent(M, evTopk2, 0);
    attn_kernel<<<HT, 512, ATTN_SMEM, M>>>(qkey, kvkey, topk, olth, oltl, HT);
    cudaStreamWaitEvent(M, evW, 0);
    gemm_nt_mma<<<dim3(1, 8, 16), 256, MMASM, M>>>(
        olth, oltl, kKVLR, (long long)kT * kKVLR,
        wkvbh + (long long)kNOPE * kKVLR, wkvbl + (long long)kNOPE * kKVLR,
        kKVLR, (long long)256 * kKVLR,
        outv, kH * kVD, kVD, kVD, kKVLR);
    splitOn(M, outv, ovh, ovl, kT * kDIM);
    gemm_nt_mma<<<dim3(16, 8, 1), 256, MMASM, M>>>(
        ovh, ovl, kDIM, 0, woh, wol, kDIM, 0,
        out, kDIM, 0, kDIM, kDIM);
}

// round 16
// speedup vs baseline: 1.0963x; 1.0963x over previous
#include <cuda_runtime.h>
#include <cuda_bf16.h>
#include <math.h>

// Problem constants
constexpr int kT    = 1024;
constexpr int kDIM  = 2048;
constexpr int kH    = 16;
constexpr int kQLR  = 1024;
constexpr int kKVLR = 512;
constexpr int kNOPE = 128;
constexpr int kROPE = 64;
constexpr int kVD   = 128;
constexpr int kQKD  = 192;
constexpr int kIH   = 16;
constexpr int kID   = 128;
constexpr int kTOPK = 256;
constexpr int kCKEY = kKVLR + kROPE; // 576

// ---------------- scratch (static device globals; no allocation) -------------
__device__ float g_qr    [kT * kQLR];
__device__ float g_iqrn  [kT * kQLR];
__device__ float g_iq    [kT * kIH * kID];
__device__ float g_ik    [kT * kIH * kID];
__device__ float g_wgt   [kT * kIH];
__device__ float g_score [kT * kT];
__device__ int   g_topk  [kT * kTOPK];
__device__ float g_q     [kT * kH * kQKD];
__device__ float g_kva   [kT * kCKEY];
__device__ float g_kvkey [kT * kCKEY];
__device__ float g_qkey  [kT * kH * kCKEY];
__device__ float g_outv  [kT * kH * kVD];

// bf16 hi/lo pairs for the HMMA attention path
__device__ __nv_bfloat16 g_xh   [kT * kDIM],          g_xl   [kT * kDIM];
__device__ __nv_bfloat16 g_wqbh [kH * kQKD * kQLR],   g_wqbl [kH * kQKD * kQLR];
__device__ __nv_bfloat16 g_wkvah[kCKEY * kDIM],       g_wkval[kCKEY * kDIM];
__device__ __nv_bfloat16 g_wkvbh[kH * 256 * kKVLR],   g_wkvbl[kH * 256 * kKVLR];
__device__ __nv_bfloat16 g_woh  [kDIM * kDIM],        g_wol  [kDIM * kDIM];
__device__ __nv_bfloat16 g_qnh  [kT * kQLR],          g_qnl  [kT * kQLR];
__device__ __nv_bfloat16 g_qbth [kH * kT * kNOPE],    g_qbtl [kH * kT * kNOPE];
__device__ __nv_bfloat16 g_wkth [kH * kKVLR * kNOPE], g_wktl [kH * kKVLR * kNOPE];
__device__ __nv_bfloat16 g_olth [kH * kT * kKVLR],    g_oltl [kH * kT * kKVLR];
__device__ __nv_bfloat16 g_ovh  [kT * kDIM],          g_ovl  [kT * kDIM];

__device__ __forceinline__ float warp_sum(float v) {
#pragma unroll
    for (int o = 16; o; o >>= 1) v += __shfl_xor_sync(0xffffffffu, v, o);
    return v;
}

// =============================================================================
// gemm64 (score path): C[m,n] = sum_k A[m,k]*B[n,k]  (fp32, NT)
// Per-element FFMA chain (serial k order) identical to all passing rounds ->
// bit-stable top-k. K-chunk 16, double-buffered smem + register prefetch.
// =============================================================================
__global__ void __launch_bounds__(64) gemm64(
    const float* __restrict__ A, int lda,
    const float* __restrict__ B, int ldb,
    float* __restrict__ C, int ldc,
    int N, int K)
{
    __shared__ float As[2][16][64];
    __shared__ float Bs[2][16][64];
    int m0 = blockIdx.y * 64, n0 = blockIdx.x * 64;
    int tid = threadIdx.x;
    int tx = tid & 7, ty = tid >> 3;
    int lrow = tid >> 1;
    int lpc  = (tid & 1) * 4;

    float acc[8][8];
#pragma unroll
    for (int i = 0; i < 8; i++)
#pragma unroll
        for (int j = 0; j < 8; j++) acc[i][j] = 0.f;

    float4 va[2][2], vb[2][2];
    auto ldg = [&](int k0) {
#pragma unroll
        for (int i = 0; i < 2; i++) {
            int row = lrow + i * 32;
            bool bok = (n0 + row) < N;
#pragma unroll
            for (int p = 0; p < 2; p++) {
                int kp = lpc + p * 8;
                va[i][p] = *(const float4*)(A + (long long)(m0 + row) * lda + k0 + kp);
                vb[i][p] = make_float4(0.f, 0.f, 0.f, 0.f);
                if (bok)
                    vb[i][p] = *(const float4*)(B + (long long)(n0 + row) * ldb + k0 + kp);
            }
        }
    };

    const int nch = K >> 4;
    ldg(0);
    for (int c = 0; c < nch; c++) {
        int buf = c & 1;
#pragma unroll
        for (int i = 0; i < 2; i++) {
            int row = lrow + i * 32;
#pragma unroll
            for (int p = 0; p < 2; p++) {
                int kp = lpc + p * 8;
                As[buf][kp + 0][row] = va[i][p].x; As[buf][kp + 1][row] = va[i][p].y;
                As[buf][kp + 2][row] = va[i][p].z; As[buf][kp + 3][row] = va[i][p].w;
                Bs[buf][kp + 0][row] = vb[i][p].x; Bs[buf][kp + 1][row] = vb[i][p].y;
                Bs[buf][kp + 2][row] = vb[i][p].z; Bs[buf][kp + 3][row] = vb[i][p].w;
            }
        }
        __syncthreads();
        if (c + 1 < nch) ldg((c + 1) << 4);
#pragma unroll
        for (int k = 0; k < 16; k++) {
            float a[8], b[8];
            *(float4*)&a[0] = *(const float4*)&As[buf][k][ty * 8];
            *(float4*)&a[4] = *(const float4*)&As[buf][k][ty * 8 + 4];
            *(float4*)&b[0] = *(const float4*)&Bs[buf][k][tx * 8];
            *(float4*)&b[4] = *(const float4*)&Bs[buf][k][tx * 8 + 4];
#pragma unroll
            for (int i = 0; i < 8; i++)
#pragma unroll
                for (int j = 0; j < 8; j++) acc[i][j] += a[i] * b[j];
        }
    }
#pragma unroll
    for (int i = 0; i < 8; i++) {
        int m = m0 + ty * 8 + i;
#pragma unroll
        for (int j = 0; j < 8; j++) {
            int n = n0 + tx * 8 + j;
            if (n < N) C[(long long)m * ldc + n] = acc[i][j];
        }
    }
}

// =============================================================================
// bf16x3 HMMA NT GEMM (attention path, smooth): AhBh + AhBl + AlBh.
// =============================================================================
__device__ __forceinline__ unsigned cvta_shared_u32(const void* p) {
    unsigned a;
    asm("{ .reg .u64 t; cvta.to.shared.u64 t, %1; cvt.u32.u64 %0, t; }"
        : "=r"(a) : "l"(p));
    return a;
}
__device__ __forceinline__ void cp16(unsigned dst, const void* src, unsigned sz) {
    asm volatile("cp.async.cg.shared.global [%0], [%1], 16, %2;"
                 :: "r"(dst), "l"(src), "r"(sz));
}
__device__ __forceinline__ void cp16ca(unsigned dst, const void* src) {
    asm volatile("cp.async.ca.shared.global [%0], [%1], 16;"
                 :: "r"(dst), "l"(src));
}
__device__ __forceinline__ void cp_commit() { asm volatile("cp.async.commit_group;"); }
__device__ __forceinline__ void cp_wait1()  { asm volatile("cp.async.wait_group 1;"); }
__device__ __forceinline__ void cp_wait0()  { asm volatile("cp.async.wait_group 0;"); }
__device__ __forceinline__ void ldsm4(unsigned& r0, unsigned& r1, unsigned& r2,
                                      unsigned& r3, unsigned addr) {
    asm volatile("ldmatrix.sync.aligned.m8n8.x4.shared.b16 {%0,%1,%2,%3}, [%4];"
                 : "=r"(r0), "=r"(r1), "=r"(r2), "=r"(r3) : "r"(addr));
}
__device__ __forceinline__ void mma_bf16(float& c0, float& c1, float& c2, float& c3,
                                         unsigned a0, unsigned a1, unsigned a2,
                                         unsigned a3, unsigned b0, unsigned b1) {
    asm volatile(
        "mma.sync.aligned.m16n8k16.row.col.f32.bf16.bf16.f32 "
        "{%0,%1,%2,%3}, {%4,%5,%6,%7}, {%8,%9}, {%0,%1,%2,%3};"
        : "+f"(c0), "+f"(c1), "+f"(c2), "+f"(c3)
        : "r"(a0), "r"(a1), "r"(a2), "r"(a3), "r"(b0), "r"(b1));
}

constexpr int kPitch  = 80;
constexpr int kMatB   = 128 * kPitch;
constexpr int kStageB = 4 * kMatB;

__global__ void __launch_bounds__(256) gemm_nt_mma(
    const __nv_bfloat16* __restrict__ Ah, const __nv_bfloat16* __restrict__ Al,
    int lda, long long sA,
    const __nv_bfloat16* __restrict__ Bh, const __nv_bfloat16* __restrict__ Bl,
    int ldb, long long sB,
    float* __restrict__ C, int ldc, long long sC,
    int N, int K)
{
    extern __shared__ char smem[];
    const unsigned sbase = cvta_shared_u32(smem);
    const int z = blockIdx.z;
    Ah += z * sA; Al += z * sA; Bh += z * sB; Bl += z * sB; C += z * sC;
    const int tid = threadIdx.x;
    const int wid = tid >> 5, lane = tid & 31;
    const int m0 = blockIdx.y * 128, n0 = blockIdx.x * 128;
    const int wm0 = (wid & 1) * 64;
    const int wn0 = (wid >> 1) * 32;

    float acc[4][4][4];
#pragma unroll
    for (int i = 0; i < 4; i++)
#pragma unroll
        for (int j = 0; j < 4; j++)
#pragma unroll
            for (int e = 0; e < 4; e++) acc[i][j][e] = 0.f;

    const int nch = K >> 5;

    auto issue_stage = [&](int c, int buf) {
        const int k0 = c << 5;
        const unsigned stage = sbase + buf * kStageB;
#pragma unroll
        for (int i = 0; i < 8; i++) {
            int idx = tid + (i << 8);
            int mat = idx >> 9, row = (idx >> 2) & 127, piece = idx & 3;
            unsigned dst = stage + mat * kMatB + row * kPitch + piece * 16;
            const __nv_bfloat16* srcp;
            unsigned sz = 16;
            if (mat == 0)      srcp = Ah + (size_t)(m0 + row) * lda + k0 + piece * 8;
            else if (mat == 1) srcp = Al + (size_t)(m0 + row) * lda + k0 + piece * 8;
            else {
                int r = n0 + row;
                int rr = (r < N) ? r : 0;
                sz = (r < N) ? 16u : 0u;
                srcp = ((mat == 2) ? Bh : Bl) + (size_t)rr * ldb + k0 + piece * 8;
            }
            cp16(dst, srcp, sz);
        }
    };

    issue_stage(0, 0); cp_commit();
    if (nch > 1) issue_stage(1, 1);
    cp_commit();

    const int rowA = wm0 + (lane & 15);
    const int kA   = (lane >> 4) << 3;
    const int rowB = wn0 + (lane & 15);
    const int kB   = (lane >> 4) << 3;

    for (int c = 0; c < nch; c++) {
        cp_wait1();
        __syncthreads();
        const unsigned stage = sbase + (c & 1) * kStageB;
        const unsigned aHb = stage;
        const unsigned aLb = stage + kMatB;
        const unsigned bHb = stage + 2 * kMatB;
        const unsigned bLb = stage + 3 * kMatB;

#pragma unroll
        for (int ks = 0; ks < 2; ks++) {
            const int kb = ks << 4;
            unsigned ah[4][4], al[4][4], bh[4][2], bl[4][2];
#pragma unroll
            for (int i = 0; i < 4; i++) {
                unsigned off = (unsigned)((rowA + 16 * i) * kPitch + (kb + kA) * 2);
                ldsm4(ah[i][0], ah[i][1], ah[i][2], ah[i][3], aHb + off);
                ldsm4(al[i][0], al[i][1], al[i][2], al[i][3], aLb + off);
            }
#pragma unroll
            for (int p = 0; p < 2; p++) {
                unsigned off = (unsigned)((rowB + 16 * p) * kPitch + (kb + kB) * 2);
                unsigned r0, r1, r2, r3;
                ldsm4(r0, r1, r2, r3, bHb + off);
                bh[2 * p][0] = r0; bh[2 * p][1] = r2;
                bh[2 * p + 1][0] = r1; bh[2 * p + 1][1] = r3;
                ldsm4(r0, r1, r2, r3, bLb + off);
                bl[2 * p][0] = r0; bl[2 * p][1] = r2;
                bl[2 * p + 1][0] = r1; bl[2 * p + 1][1] = r3;
            }
#pragma unroll
            for (int i = 0; i < 4; i++)
#pragma unroll
                for (int j = 0; j < 4; j++) {
                    mma_bf16(acc[i][j][0], acc[i][j][1], acc[i][j][2], acc[i][j][3],
                             ah[i][0], ah[i][1], ah[i][2], ah[i][3],
                             bh[j][0], bh[j][1]);
                    mma_bf16(acc[i][j][0], acc[i][j][1], acc[i][j][2], acc[i][j][3],
                             ah[i][0], ah[i][1], ah[i][2], ah[i][3],
                             bl[j][0], bl[j][1]);
                    mma_bf16(acc[i][j][0], acc[i][j][1], acc[i][j][2], acc[i][j][3],
                             al[i][0], al[i][1], al[i][2], al[i][3],
                             bh[j][0], bh[j][1]);
                }
        }
        __syncthreads();
        if (c + 2 < nch) issue_stage(c + 2, c & 1);
        cp_commit();
    }
    cp_wait0();

    const int erow = lane >> 2;
    const int ecol = (lane & 3) * 2;
#pragma unroll
    for (int i = 0; i < 4; i++)
#pragma unroll
        for (int j = 0; j < 4; j++) {
            int n = n0 + wn0 + 8 * j + ecol;
            if (n < N) {
                int m = m0 + wm0 + 16 * i + erow;
                *(float2*)(C + (size_t)m * ldc + n) =
                    make_float2(acc[i][j][0], acc[i][j][1]);
                *(float2*)(C + (size_t)(m + 8) * ldc + n) =
                    make_float2(acc[i][j][2], acc[i][j][3]);
            }
        }
}

// ---------------- fp32 -> bf16 hi/lo split ------------------------------------
__device__ __forceinline__ unsigned short bfu(__nv_bfloat16 b) {
    return *reinterpret_cast<unsigned short*>(&b);
}
__global__ void split_kernel(const float4* __restrict__ in,
                             uint2* __restrict__ hi, uint2* __restrict__ lo, int n4)
{
    int i = blockIdx.x * 256 + threadIdx.x;
    if (i >= n4) return;
    float4 v = in[i];
    __nv_bfloat16 hx = __float2bfloat16(v.x), hy = __float2bfloat16(v.y);
    __nv_bfloat16 hz = __float2bfloat16(v.z), hw = __float2bfloat16(v.w);
    __nv_bfloat16 lx = __float2bfloat16(v.x - __bfloat162float(hx));
    __nv_bfloat16 ly = __float2bfloat16(v.y - __bfloat162float(hy));
    __nv_bfloat16 lz = __float2bfloat16(v.z - __bfloat162float(hz));
    __nv_bfloat16 lw = __float2bfloat16(v.w - __bfloat162float(hw));
    uint2 ho, loo;
    ho.x  = (unsigned)bfu(hx) | ((unsigned)bfu(hy) << 16);
    ho.y  = (unsigned)bfu(hz) | ((unsigned)bfu(hw) << 16);
    loo.x = (unsigned)bfu(lx) | ((unsigned)bfu(ly) << 16);
    loo.y = (unsigned)bfu(lz) | ((unsigned)bfu(lw) << 16);
    hi[i] = ho; lo[i] = loo;
}

// =============================================================================
// SCORE-PATH ELEMENTWISE KERNELS — numerics unchanged from passing rounds.
// =============================================================================

__global__ void qrnorm_kernel(const float* __restrict__ qr,
                              const float* __restrict__ qnw,
                              const float* __restrict__ iqnw,
                              __nv_bfloat16* __restrict__ qh,
                              __nv_bfloat16* __restrict__ ql,
                              float* __restrict__ iqn)
{
    int t = blockIdx.x;
    __shared__ float sred[16];
    float s = 0.f;
    for (int i = threadIdx.x; i < kQLR; i += 512) {
        float v = qr[t * kQLR + i]; s += v * v;
    }
    s = warp_sum(s);
    if ((threadIdx.x & 31) == 0) sred[threadIdx.x >> 5] = s;
    __syncthreads();
    float tot = 0.f;
#pragma unroll
    for (int i = 0; i < 16; i++) tot += sred[i];
    float rstd = rsqrtf(tot * (1.f / kQLR) + 1e-6f);
    for (int i = threadIdx.x; i < kQLR; i += 512) {
        float v = qr[t * kQLR + i] * rstd;
        float a = v * qnw[i];
        __nv_bfloat16 h = __float2bfloat16(a);
        qh[t * kQLR + i] = h;
        ql[t * kQLR + i] = __float2bfloat16(a - __bfloat162float(h));
        iqn[t * kQLR + i] = v * iqnw[i];
    }
}

__global__ void idx_prep_kernel(float* __restrict__ data,
                                const float* __restrict__ rc,
                                const float* __restrict__ rs,
                                const float* __restrict__ lnw,
                                const float* __restrict__ lnb,
                                int do_ln)
{
    int t = blockIdx.x >> 4;
    int h = blockIdx.x & 15;
    float* v = data + (size_t)t * (kIH * kID) + h * kID;
    int d = threadIdx.x;
    __shared__ float sv[128];
    __shared__ float sred[4];
    float x = v[d];
    if (do_ln) {
        float s = warp_sum(x);
        if ((d & 31) == 0) sred[d >> 5] = s;
        __syncthreads();
        float mean = (sred[0] + sred[1] + sred[2] + sred[3]) * (1.f / 128.f);
        float c = x - mean;
        __syncthreads();
        float s2 = warp_sum(c * c);
        if ((d & 31) == 0) sred[d >> 5] = s2;
        __syncthreads();
        float var = (sred[0] + sred[1] + sred[2] + sred[3]) * (1.f / 128.f);
        x = c * rsqrtf(var + 1e-5f) * lnw[d] + lnb[d];
    }
    sv[d] = x;
    __syncthreads();
    float out;
    if (d < 32) {
        out = sv[d] * rc[t * 32 + d] - sv[d + 32] * rs[t * 32 + d];
    } else if (d < 64) {
        int j = d - 32;
        out = sv[j] * rs[t * 32 + j] + sv[j + 32] * rc[t * 32 + j];
    } else {
        out = x;
    }
    v[d] = out;
}

__global__ void wgt_kernel(const float* __restrict__ x,
                           const float* __restrict__ wproj,
                           float* __restrict__ wgt)
{
    int t = blockIdx.x;
    __shared__ float sx[kDIM];
    for (int i = threadIdx.x; i < kDIM; i += 512) sx[i] = x[(size_t)t * kDIM + i];
    __syncthreads();
    int w = threadIdx.x >> 5, lane = threadIdx.x & 31;
    float acc = 0.f;
    for (int i = lane; i < kDIM; i += 32) acc += sx[i] * wproj[w * kDIM + i];
    acc = warp_sum(acc);
    if (lane == 0) wgt[t * kIH + w] = acc * 0.022097086912079613f;
}

__global__ void __launch_bounds__(256) score_kernel(
    const float* __restrict__ iq, const float* __restrict__ ik,
    const float* __restrict__ wgt, float* __restrict__ score)
{
    int s0 = blockIdx.x * 64, t0 = blockIdx.y * 64;
    if (s0 > t0 + 63) return;
    __shared__ float As[16][64], Bs[16][64];
    int tid = threadIdx.x;
    int tx = tid & 15, ty = tid >> 4;
    int r = tid >> 2, kq = (tid & 3) * 4;
    float acc[4][4];
#pragma unroll
    for (int i = 0; i < 4; i++)
#pragma unroll
        for (int j = 0; j < 4; j++) acc[i][j] = 0.f;

    for (int h = 0; h < 16; h++) {
        float hacc[4][4];
#pragma unroll
        for (int i = 0; i < 4; i++)
#pragma unroll
            for (int j = 0; j < 4; j++) hacc[i][j] = 0.f;
        for (int k0 = 0; k0 < 128; k0 += 16) {
            float4 av = *(const float4*)&iq[(size_t)(t0 + r) * 2048 + h * 128 + k0 + kq];
            float4 bv = *(const float4*)&ik[(size_t)(s0 + r) * 2048 + h * 128 + k0 + kq];
            As[kq][r] = av.x; As[kq + 1][r] = av.y;
            As[kq + 2][r] = av.z; As[kq + 3][r] = av.w;
            Bs[kq][r] = bv.x; Bs[kq + 1][r] = bv.y;
            Bs[kq + 2][r] = bv.z; Bs[kq + 3][r] = bv.w;
            __syncthreads();
#pragma unroll
            for (int k = 0; k < 16; k++) {
                float a[4], b[4];
#pragma unroll
                for (int i = 0; i < 4; i++) a[i] = As[k][ty * 4 + i];
#pragma unroll
                for (int j = 0; j < 4; j++) b[j] = Bs[k][tx * 4 + j];
#pragma unroll
                for (int i = 0; i < 4; i++)
#pragma unroll
                    for (int j = 0; j < 4; j++) hacc[i][j] += a[i] * b[j];
            }
            __syncthreads();
        }
#pragma unroll
        for (int i = 0; i < 4; i++) {
            float wv = wgt[(t0 + ty * 4 + i) * kIH + h];
#pragma unroll
            for (int j = 0; j < 4; j++)
                acc[i][j] += fmaxf(hacc[i][j], 0.f) * wv;
        }
    }
#pragma unroll
    for (int i = 0; i < 4; i++)
#pragma unroll
        for (int j = 0; j < 4; j++)
            score[(size_t)(t0 + ty * 4 + i) * kT + s0 + tx * 4 + j] = acc[i][j];
}

__global__ void __launch_bounds__(512) topk_kernel(const float* __restrict__ score,
                                                   int* __restrict__ topk)
{
    int t = blockIdx.x;
    __shared__ unsigned long long keys[1024];
    for (int i = threadIdx.x; i < 1024; i += 512) {
        float v = (i <= t) ? score[(size_t)t * kT + i] : __int_as_float(0xff800000);
        unsigned int fb = __float_as_uint(v);
        fb = (fb & 0x80000000u) ? ~fb : (fb | 0x80000000u);
        keys[i] = ((unsigned long long)fb << 32) | (unsigned int)(1023 - i);
    }
    __syncthreads();
    for (int k = 2; k <= 1024; k <<= 1) {
        for (int j = k >> 1; j > 0; j >>= 1) {
            for (int i = threadIdx.x; i < 1024; i += 512) {
                int ixj = i ^ j;
                if (ixj > i) {
                    unsigned long long a = keys[i], b = keys[ixj];
                    bool seg = ((i & k) == 0);
                    bool sw = seg ? (a < b) : (a > b);
                    if (sw) { keys[i] = b; keys[ixj] = a; }
                }
            }
            __syncthreads();
        }
    }
    if (threadIdx.x < 256)
        topk[t * kTOPK + threadIdx.x] =
            1023 - (int)(keys[threadIdx.x] & 0xFFFFFFFFu);
}

// =============================================================================
// ATTENTION PATH helpers
// =============================================================================

__global__ void wk_transpose(const float* __restrict__ wkv_b,
                             __nv_bfloat16* __restrict__ wkTh,
                             __nv_bfloat16* __restrict__ wkTl)
{
    __shared__ float tile[32][33];
    int h = blockIdx.z;
    int c0 = blockIdx.x * 32, d0 = blockIdx.y * 32;
    int tx = threadIdx.x, ty = threadIdx.y;
#pragma unroll
    for (int k = 0; k < 4; k++)
        tile[ty + 8 * k][tx] = wkv_b[(size_t)(h * 256 + d0 + ty + 8 * k) * 512 + c0 + tx];
    __syncthreads();
#pragma unroll
    for (int k = 0; k < 4; k++) {
        float v = tile[tx][ty + 8 * k];
        size_t o = (size_t)h * 65536 + (size_t)(c0 + ty + 8 * k) * 128 + d0 + tx;
        __nv_bfloat16 hh = __float2bfloat16(v);
        wkTh[o] = hh;
        wkTl[o] = __float2bfloat16(v - __bfloat162float(hh));
    }
}

// merged qb_repack + qprep: one pass over qb produces the bf16 hi/lo repack
// (for the q_nope HMMA gemm) AND the roped q_pe columns of qkey. Per-element
// arithmetic identical to the previous two kernels.
__global__ void qb_prep_kernel(const float* __restrict__ qb,
                               const float* __restrict__ rc,
                               const float* __restrict__ rs,
                               __nv_bfloat16* __restrict__ qbth,
                               __nv_bfloat16* __restrict__ qbtl,
                               float* __restrict__ qkey)
{
    int t = blockIdx.x;
    // repack part: 2048 elements (16 heads x 128 dims)
    for (int i = threadIdx.x; i < 2048; i += 512) {
        int h = i >> 7, d = i & 127;
        float v = qb[(size_t)t * 3072 + h * 192 + d];
        size_t o = (size_t)(h * 1024 + t) * 128 + d;
        __nv_bfloat16 hh = __float2bfloat16(v);
        qbth[o] = hh;
        qbtl[o] = __float2bfloat16(v - __bfloat162float(hh));
    }
    // rope part: 16 heads x 32 pairs (512 threads exactly)
    {
        int h = threadIdx.x >> 5, j = threadIdx.x & 31;
        const float* b = qb + (size_t)t * (kH * kQKD) + h * kQKD;
        float x1 = b[128 + j], x2 = b[160 + j];
        float c = rc[t * 32 + j], sn = rs[t * 32 + j];
        float* o = qkey + (size_t)t * (kH * kCKEY) + h * kCKEY;
        o[512 + j] = x1 * c - x2 * sn;
        o[544 + j] = x1 * sn + x2 * c;
    }
}

__global__ void kvprep_kernel(const float* __restrict__ kva,
                              const float* __restrict__ kvnw,
                              const float* __restrict__ rc,
                              const float* __restrict__ rs,
                              float* __restrict__ kvkey)
{
    int t = blockIdx.x, tid = threadIdx.x;
    __shared__ float sred[16];
    float x = kva[(size_t)t * kCKEY + tid];
    float s = warp_sum(x * x);
    if ((tid & 31) == 0) sred[tid >> 5] = s;
    __syncthreads();
    float tot = 0.f;
#pragma unroll
    for (int i = 0; i < 16; i++) tot += sred[i];
    float rstd = rsqrtf(tot * (1.f / kKVLR) + 1e-6f);
    kvkey[(size_t)t * kCKEY + tid] = x * rstd * kvnw[tid];
    if (tid < 32) {
        float x1 = kva[(size_t)t * kCKEY + 512 + tid];
        float x2 = kva[(size_t)t * kCKEY + 544 + tid];
        float c = rc[t * 32 + tid], sn = rs[t * 32 + tid];
        kvkey[(size_t)t * kCKEY + 512 + tid] = x1 * c - x2 * sn;
        kvkey[(size_t)t * kCKEY + 544 + tid] = x1 * sn + x2 * c;
    }
}

// fused sparse attention -> out_latent emitted as bf16 hi/lo in [h][t][c]
__global__ void __launch_bounds__(512) attn_kernel(
    const float* __restrict__ qkey, const float* __restrict__ kvkey,
    const int* __restrict__ topk,
    __nv_bfloat16* __restrict__ olth, __nv_bfloat16* __restrict__ oltl)
{
    extern __shared__ float sm[];
    float* sq    = sm;                  // 9216
    float* stile = sm + 9216;           // 2 x 9216 (double buffered, pitch 36)
    float* slog2 = sm + 9216;           // reuse of stileA (256 x pitch 20)
    float* slog  = sm + 27648;          // 4096 ([h][k])
    int*   sidx  = (int*)(sm + 31744);  // 256
    const unsigned stile_u32 = cvta_shared_u32(stile);
    int t = blockIdx.x, tid = threadIdx.x;
    for (int i = tid; i < 9216; i += 512) sq[i] = qkey[(size_t)t * 9216 + i];
    if (tid < 256) sidx[tid] = topk[t * kTOPK + tid];
    __syncthreads();

    const float scale = 0.07216878364870323f; // 192^-0.5

    // phase 1: logits = sel(256x576) @ q^T(576x16), cp.async double-buffered
    {
        int rg = tid >> 3;
        int hg = tid & 7;
        float pacc[4][2];
#pragma unroll
        for (int i = 0; i < 4; i++) { pacc[i][0] = 0.f; pacc[i][1] = 0.f; }

        auto issue = [&](int cc, int buf) {
            int c0 = cc * 32;
#pragma unroll
            for (int i = 0; i < 4; i++) {
                int idx = tid + 512 * i;
                int r = idx >> 3;
                int p = (idx & 7) * 4;
                cp16ca(stile_u32 + (unsigned)(buf * 9216 + r * 36 + p) * 4u,
                       &kvkey[(size_t)sidx[r] * kCKEY + c0 + p]);
            }
        };

        issue(0, 0); cp_commit();
        for (int cc = 0; cc < 18; cc++) {
            int buf = cc & 1;
            cp_wait0();
            __syncthreads();
            if (cc + 1 < 18) { issue(cc + 1, 1 - buf); cp_commit(); }
            const float* st = stile + buf * 9216;
#pragma unroll
            for (int c4 = 0; c4 < 8; c4++) {
                int c0 = cc * 32;
                float4 q0 = *(const float4*)&sq[(hg * 2 + 0) * kCKEY + c0 + c4 * 4];
                float4 q1 = *(const float4*)&sq[(hg * 2 + 1) * kCKEY + c0 + c4 * 4];
#pragma unroll
                for (int i = 0; i < 4; i++) {
                    float4 s = *(const float4*)&st[(rg * 4 + i) * 36 + c4 * 4];
                    pacc[i][0] += s.x * q0.x + s.y * q0.y + s.z * q0.z + s.w * q0.w;
                    pacc[i][1] += s.x * q1.x + s.y * q1.y + s.z * q1.z + s.w * q1.w;
                }
            }
        }
        __syncthreads();
#pragma unroll
        for (int i = 0; i < 4; i++) {
            int k = rg * 4 + i;
            int idx = sidx[k];
            float ninf = __int_as_float(0xff800000);
#pragma unroll
            for (int hh = 0; hh < 2; hh++) {
                int h = hg * 2 + hh;
                slog[h * 256 + k] = (idx <= t) ? pacc[i][hh] * scale : ninf;
            }
        }
    }
    __syncthreads();

    // softmax per head -> slog2 in [k][pitch 20]
    {
        int hh = tid >> 5, lane = tid & 31;
        float vals[8];
        float m = __int_as_float(0xff800000);
#pragma unroll
        for (int i = 0; i < 8; i++) {
            vals[i] = slog[hh * 256 + lane + 32 * i];
            m = fmaxf(m, vals[i]);
        }
#pragma unroll
        for (int o = 16; o; o >>= 1) m = fmaxf(m, __shfl_xor_sync(0xffffffffu, m, o));
        float s = 0.f;
#pragma unroll
        for (int i = 0; i < 8; i++) {
            float e = (vals[i] > -1e30f) ? __expf(vals[i] - m) : 0.f;
            vals[i] = e; s += e;
        }
        s = warp_sum(s);
        float inv = 1.f / s;
        __syncthreads();
#pragma unroll
        for (int i = 0; i < 8; i++)
            slog2[(lane + 32 * i) * 20 + hh] = vals[i] * inv;
    }
    __syncthreads();

    // phase 2
    {
        int c = tid;
        float acc[16];
#pragma unroll
        for (int i = 0; i < 16; i++) acc[i] = 0.f;
        for (int k = 0; k < 256; k++) {
            float v = kvkey[(size_t)sidx[k] * kCKEY + c];
            float4 w0 = *(const float4*)&slog2[k * 20 + 0];
            float4 w1 = *(const float4*)&slog2[k * 20 + 4];
            float4 w2 = *(const float4*)&slog2[k * 20 + 8];
            float4 w3 = *(const float4*)&slog2[k * 20 + 12];
            acc[0]  += w0.x * v; acc[1]  += w0.y * v; acc[2]  += w0.z * v; acc[3]  += w0.w * v;
            acc[4]  += w1.x * v; acc[5]  += w1.y * v; acc[6]  += w1.z * v; acc[7]  += w1.w * v;
            acc[8]  += w2.x * v; acc[9]  += w2.y * v; acc[10] += w2.z * v; acc[11] += w2.w * v;
            acc[12] += w3.x * v; acc[13] += w3.y * v; acc[14] += w3.z * v; acc[15] += w3.w * v;
        }
#pragma unroll
        for (int hh = 0; hh < 16; hh++) {
            float v = acc[hh];
            size_t o = (size_t)(hh * kT + t) * kKVLR + c;
            __nv_bfloat16 h = __float2bfloat16(v);
            olth[o] = h;
            oltl[o] = __float2bfloat16(v - __bfloat162float(h));
        }
    }
}

// ---------------- host launch -------------------------------------------------
static inline void splitOn(cudaStream_t s, const float* src,
                           __nv_bfloat16* h, __nv_bfloat16* l, int n) {
    int n4 = n / 4;
    split_kernel<<<(n4 + 255) / 256, 256, 0, s>>>((const float4*)src,
                                                  (uint2*)h, (uint2*)l, n4);
}

extern "C" void kernel_launch(void* const* d_in, const int* in_sizes, int n_in,
                              void* d_out, int out_size)
{
    const float* x        = (const float*)d_in[0];
    const float* rc       = (const float*)d_in[1];
    const float* rs       = (const float*)d_in[2];
    const float* wq_a     = (const float*)d_in[3];
    const float* q_norm_w = (const float*)d_in[4];
    const float* wq_b     = (const float*)d_in[5];
    const float* wkv_a    = (const float*)d_in[6];
    const float* kv_norm_w= (const float*)d_in[7];
    const float* wkv_b    = (const float*)d_in[8];
    const float* wo       = (const float*)d_in[9];
    const float* iq_norm_w= (const float*)d_in[10];
    const float* iwq_b    = (const float*)d_in[11];
    const float* iwk      = (const float*)d_in[12];
    const float* k_norm_w = (const float*)d_in[13];
    const float* k_norm_b = (const float*)d_in[14];
    const float* wproj    = (const float*)d_in[15];
    float* out = (float*)d_out;

    float *qr, *iqrn, *iqb, *ikb, *wgt, *score, *qb, *kva, *kvkey, *qkey, *outv;
    int* topk;
    __nv_bfloat16 *xh, *xl, *wqbh, *wqbl, *wkvah, *wkval, *wkvbh, *wkvbl, *woh, *wol;
    __nv_bfloat16 *qnh, *qnl, *qbth, *qbtl, *wkth, *wktl, *olth, *oltl, *ovh, *ovl;

    cudaGetSymbolAddress((void**)&qr,    g_qr);
    cudaGetSymbolAddress((void**)&iqrn,  g_iqrn);
    cudaGetSymbolAddress((void**)&iqb,   g_iq);
    cudaGetSymbolAddress((void**)&ikb,   g_ik);
    cudaGetSymbolAddress((void**)&wgt,   g_wgt);
    cudaGetSymbolAddress((void**)&score, g_score);
    cudaGetSymbolAddress((void**)&topk,  g_topk);
    cudaGetSymbolAddress((void**)&qb,    g_q);
    cudaGetSymbolAddress((void**)&kva,   g_kva);
    cudaGetSymbolAddress((void**)&kvkey, g_kvkey);
    cudaGetSymbolAddress((void**)&qkey,  g_qkey);
    cudaGetSymbolAddress((void**)&outv,  g_outv);
    cudaGetSymbolAddress((void**)&xh,    g_xh);    cudaGetSymbolAddress((void**)&xl,    g_xl);
    cudaGetSymbolAddress((void**)&wqbh,  g_wqbh);  cudaGetSymbolAddress((void**)&wqbl,  g_wqbl);
    cudaGetSymbolAddress((void**)&wkvah, g_wkvah); cudaGetSymbolAddress((void**)&wkval, g_wkval);
    cudaGetSymbolAddress((void**)&wkvbh, g_wkvbh); cudaGetSymbolAddress((void**)&wkvbl, g_wkvbl);
    cudaGetSymbolAddress((void**)&woh,   g_woh);   cudaGetSymbolAddress((void**)&wol,   g_wol);
    cudaGetSymbolAddress((void**)&qnh,   g_qnh);   cudaGetSymbolAddress((void**)&qnl,   g_qnl);
    cudaGetSymbolAddress((void**)&qbth,  g_qbth);  cudaGetSymbolAddress((void**)&qbtl,  g_qbtl);
    cudaGetSymbolAddress((void**)&wkth,  g_wkth);  cudaGetSymbolAddress((void**)&wktl,  g_wktl);
    cudaGetSymbolAddress((void**)&olth,  g_olth);  cudaGetSymbolAddress((void**)&oltl,  g_oltl);
    cudaGetSymbolAddress((void**)&ovh,   g_ovh);   cudaGetSymbolAddress((void**)&ovl,   g_ovl);

    const int ATTN_SMEM = (31744 + 256) * 4; // 128000 B
    cudaFuncSetAttribute(attn_kernel, cudaFuncAttributeMaxDynamicSharedMemorySize, ATTN_SMEM);
    cudaFuncSetAttribute(gemm_nt_mma, cudaFuncAttributeMaxDynamicSharedMemorySize, 2 * kStageB);
    const int MMASM = 2 * kStageB;

    static cudaStream_t s1 = nullptr;
    static cudaEvent_t evFork = nullptr, evQN = nullptr, evPrep = nullptr;
    static cudaEvent_t evTopk = nullptr, evW = nullptr;
    if (!s1) {
        cudaStreamCreateWithFlags(&s1, cudaStreamNonBlocking);
        cudaEventCreateWithFlags(&evFork,  cudaEventDisableTiming);
        cudaEventCreateWithFlags(&evQN,    cudaEventDisableTiming);
        cudaEventCreateWithFlags(&evPrep,  cudaEventDisableTiming);
        cudaEventCreateWithFlags(&evTopk,  cudaEventDisableTiming);
        cudaEventCreateWithFlags(&evW,     cudaEventDisableTiming);
    }
    cudaStream_t M = 0;

    // ---- fork ----
    cudaEventRecord(evFork, M);
    cudaStreamWaitEvent(s1, evFork, 0);

    // S1: wk_transpose (input-only), then score branch (x-only part)
    wk_transpose<<<dim3(16, 4, 16), dim3(32, 8), 0, s1>>>(wkv_b, wkth, wktl);
    cudaEventRecord(evPrep, s1);
    gemm64<<<dim3(32, 16), 64, 0, s1>>>(x, kDIM, iwk, kDIM, ikb, 2048, 2048, kDIM);
    idx_prep_kernel<<<kT * kIH, 128, 0, s1>>>(ikb, rc, rs, k_norm_w, k_norm_b, 1);
    wgt_kernel<<<kT, 512, 0, s1>>>(x, wproj, wgt);

    // M: qr + qrnorm first (feeds score branch)
    gemm64<<<dim3(16, 16), 64, 0, M>>>(x, kDIM, wq_a, kDIM, qr, kQLR, kQLR, kDIM);
    qrnorm_kernel<<<kT, 512, 0, M>>>(qr, q_norm_w, iq_norm_w, qnh, qnl, iqrn);
    cudaEventRecord(evQN, M);

    // S1: rest of score path (iq depends on qrnorm)
    cudaStreamWaitEvent(s1, evQN, 0);
    gemm64<<<dim3(32, 16), 64, 0, s1>>>(iqrn, kQLR, iwq_b, kQLR, iqb, 2048, 2048, kQLR);
    idx_prep_kernel<<<kT * kIH, 128, 0, s1>>>(iqb, rc, rs, nullptr, nullptr, 0);
    score_kernel<<<dim3(16, 16), 256, 0, s1>>>(iqb, ikb, wgt, score);
    topk_kernel<<<kT, 512, 0, s1>>>(score, topk);
    cudaEventRecord(evTopk, s1);
    // S1 post-topk: weight splits consumed only after the join
    splitOn(s1, wkv_b, wkvbh, wkvbl, kH * 256 * kKVLR);
    splitOn(s1, wo,    woh,   wol,   kDIM * kDIM);
    cudaEventRecord(evW, s1);

    // M: attention path (splits just-in-time before their consumers)
    splitOn(M, wq_b, wqbh, wqbl, kH * kQKD * kQLR);
    gemm_nt_mma<<<dim3(24, 8, 1), 256, MMASM, M>>>(
        qnh, qnl, kQLR, 0, wqbh, wqbl, kQLR, 0,
        qb, kH * kQKD, 0, kH * kQKD, kQLR);
    splitOn(M, x,     xh,    xl,    kT * kDIM);
    splitOn(M, wkv_a, wkvah, wkval, kCKEY * kDIM);
    gemm_nt_mma<<<dim3(5, 8, 1), 256, MMASM, M>>>(
        xh, xl, kDIM, 0, wkvah, wkval, kDIM, 0,
        kva, kCKEY, 0, kCKEY, kDIM);
    kvprep_kernel<<<kT, 512, 0, M>>>(kva, kv_norm_w, rc, rs, kvkey);
    qb_prep_kernel<<<kT, 512, 0, M>>>(qb, rc, rs, qbth, qbtl, qkey);
    cudaStreamWaitEvent(M, evPrep, 0);
    gemm_nt_mma<<<dim3(4, 8, 16), 256, MMASM, M>>>(
        qbth, qbtl, kNOPE, (long long)kT * kNOPE,
        wkth, wktl, kNOPE, (long long)kKVLR * kNOPE,
        qkey, kH * kCKEY, kCKEY, kKVLR, kNOPE);

    // ---- join: attn needs topk (S1) + qkey/kvkey (M) ----
    cudaStreamWaitEvent(M, evTopk, 0);
    attn_kernel<<<kT, 512, ATTN_SMEM, M>>>(qkey, kvkey, topk, olth, oltl);
    cudaStreamWaitEvent(M, evW, 0);
    gemm_nt_mma<<<dim3(1, 8, 16), 256, MMASM, M>>>(
        olth, oltl, kKVLR, (long long)kT * kKVLR,
        wkvbh + (long long)kNOPE * kKVLR, wkvbl + (long long)kNOPE * kKVLR,
        kKVLR, (long long)256 * kKVLR,
        outv, kH * kVD, kVD, kVD, kKVLR);
    splitOn(M, outv, ovh, ovl, kT * kDIM);
    gemm_nt_mma<<<dim3(16, 8, 1), 256, MMASM, M>>>(
        ovh, ovl, kDIM, 0, woh, wol, kDIM, 0,
        out, kDIM, 0, kDIM, kDIM);
}